// round 1
// baseline (speedup 1.0000x reference)
#include <cuda_runtime.h>
#include <cstdint>
#include <cstddef>

// ============================================================================
// DecagonModel: 3-layer relational GCN
//   per conv: tmp = X @ W  (dense),  out += A_coo @ tmp  (sparse, atomic)
//   layer1/2 relu, layer3 raw; output = [e0 | e0 | e3] per node type.
// Shapes: N0=30000, N1=6000, F=1024, H=512, out [36000, 1536] f32.
// ============================================================================

#define KN0 30000
#define KN1 6000
#define KF  1024
#define KH  512
#define LDO 1536

// Scratch (device globals: allocation-free rule)
__device__ float g_tmp[KN0 * KH];   // x@W scratch, reused by all 15 convs
__device__ float g_e00[KN0 * KH];   // layer-1 type-0 embedding
__device__ float g_e01[KN1 * KH];   // layer-1 type-1
__device__ float g_e20[KN0 * KH];   // layer-2 type-0
__device__ float g_e21[KN1 * KH];   // layer-2 type-1

// ----------------------------------------------------------------------------
// SGEMM: C[M,N] = A[M,K] @ B[K,N].  BM=BN=128, BK=8, 256 threads, 8x8/thread.
// N is always 512 (multiple of 128), K in {512,1024} (multiple of 8); only M ragged.
// ----------------------------------------------------------------------------
__global__ __launch_bounds__(256) void sgemm128(
    const float* __restrict__ A, const float* __restrict__ B,
    float* __restrict__ C, int M, int N, int K)
{
    __shared__ float As[8][128];   // transposed A tile: As[k][m]
    __shared__ float Bs[8][128];

    const int bm  = blockIdx.y * 128;
    const int bn  = blockIdx.x * 128;
    const int tid = threadIdx.x;

    // A tile load: 128 rows x 8 cols; one float4 along K per thread
    const int arow = tid >> 1;
    const int acol = (tid & 1) << 2;
    // B tile load: 8 rows x 128 cols; one float4 along N per thread
    const int brow = tid >> 5;
    const int bcol = (tid & 31) << 2;
    // compute mapping: 16x16 threads, 8x8 micro-tile each
    const int tr = (tid >> 4) << 3;
    const int tc = (tid & 15) << 3;

    float acc[8][8];
#pragma unroll
    for (int i = 0; i < 8; i++)
#pragma unroll
        for (int j = 0; j < 8; j++) acc[i][j] = 0.f;

    const int  gr     = bm + arow;
    const bool avalid = (gr < M);
    const float* Aptr = A + (size_t)gr * K + acol;
    const float* Bptr = B + (size_t)brow * N + bn + bcol;

    for (int k0 = 0; k0 < K; k0 += 8) {
        float4 a4 = avalid ? *reinterpret_cast<const float4*>(Aptr + k0)
                           : make_float4(0.f, 0.f, 0.f, 0.f);
        As[acol + 0][arow] = a4.x;
        As[acol + 1][arow] = a4.y;
        As[acol + 2][arow] = a4.z;
        As[acol + 3][arow] = a4.w;
        *reinterpret_cast<float4*>(&Bs[brow][bcol]) =
            *reinterpret_cast<const float4*>(Bptr + (size_t)k0 * N);
        __syncthreads();

#pragma unroll
        for (int k = 0; k < 8; k++) {
            float4 a0 = *reinterpret_cast<const float4*>(&As[k][tr]);
            float4 a1 = *reinterpret_cast<const float4*>(&As[k][tr + 4]);
            float4 b0 = *reinterpret_cast<const float4*>(&Bs[k][tc]);
            float4 b1 = *reinterpret_cast<const float4*>(&Bs[k][tc + 4]);
            float ra[8] = {a0.x, a0.y, a0.z, a0.w, a1.x, a1.y, a1.z, a1.w};
            float rb[8] = {b0.x, b0.y, b0.z, b0.w, b1.x, b1.y, b1.z, b1.w};
#pragma unroll
            for (int i = 0; i < 8; i++)
#pragma unroll
                for (int j = 0; j < 8; j++)
                    acc[i][j] = fmaf(ra[i], rb[j], acc[i][j]);
        }
        __syncthreads();
    }

#pragma unroll
    for (int i = 0; i < 8; i++) {
        int r = bm + tr + i;
        if (r < M) {
            float* Crow = C + (size_t)r * N + bn + tc;
            *reinterpret_cast<float4*>(Crow) =
                make_float4(acc[i][0], acc[i][1], acc[i][2], acc[i][3]);
            *reinterpret_cast<float4*>(Crow + 4) =
                make_float4(acc[i][4], acc[i][5], acc[i][6], acc[i][7]);
        }
    }
}

// ----------------------------------------------------------------------------
// SpMM (COO, edge-parallel): out[row[e], :] += val[e] * x[col[e], :]
// One warp per edge; row width = 512 floats = 128 float4 = 4 float4/lane.
// Vector reduction (red.global.add.v4.f32, sm_90+) — no return trip.
// ----------------------------------------------------------------------------
__global__ __launch_bounds__(256) void spmm_edges(
    const int* __restrict__ row, const int* __restrict__ col,
    const float* __restrict__ val, const float* __restrict__ x,
    float* __restrict__ out, int E, int ldo)
{
    int warp = (blockIdx.x * blockDim.x + threadIdx.x) >> 5;
    int lane = threadIdx.x & 31;
    if (warp >= E) return;

    const int   r = row[warp];
    const int   c = col[warp];
    const float v = val[warp];

    const float4* xr   = reinterpret_cast<const float4*>(x + (size_t)c * KH);
    float*        orow = out + (size_t)r * ldo;

#pragma unroll
    for (int i = 0; i < 4; i++) {
        float4 t = xr[lane + i * 32];
        float* p = orow + (size_t)(lane + i * 32) * 4;
        asm volatile(
            "red.global.add.v4.f32 [%0], {%1, %2, %3, %4};"
            :: "l"(p), "f"(t.x * v), "f"(t.y * v), "f"(t.z * v), "f"(t.w * v)
            : "memory");
    }
}

// ----------------------------------------------------------------------------
// Epilogue helpers
// ----------------------------------------------------------------------------
__global__ void zero_kernel(float* __restrict__ p, size_t n4)  // n4 = count/4
{
    size_t i = blockIdx.x * (size_t)blockDim.x + threadIdx.x;
    if (i < n4) reinterpret_cast<float4*>(p)[i] = make_float4(0.f, 0.f, 0.f, 0.f);
}

// zero d_out[:, 1024:1536) for all rows (layer-3 accumulation target)
__global__ void zero_cols(float* __restrict__ out, int nrows)
{
    int idx = blockIdx.x * blockDim.x + threadIdx.x;  // over nrows*128
    if (idx >= nrows * 128) return;
    int r = idx >> 7, c = idx & 127;
    reinterpret_cast<float4*>(out + (size_t)r * LDO + 1024)[c] =
        make_float4(0.f, 0.f, 0.f, 0.f);
}

// relu(e) in place AND write two copies into d_out cols [0,512) and [512,1024)
__global__ void relu_copy_dual(float* __restrict__ e, float* __restrict__ outbase, int n)
{
    int idx = blockIdx.x * blockDim.x + threadIdx.x;  // over n*128
    if (idx >= n * 128) return;
    float4 t = reinterpret_cast<float4*>(e)[idx];
    t.x = fmaxf(t.x, 0.f); t.y = fmaxf(t.y, 0.f);
    t.z = fmaxf(t.z, 0.f); t.w = fmaxf(t.w, 0.f);
    reinterpret_cast<float4*>(e)[idx] = t;
    int r = idx >> 7, c = idx & 127;
    float4* o = reinterpret_cast<float4*>(outbase + (size_t)r * LDO);
    o[c]       = t;
    o[c + 128] = t;
}

__global__ void relu_inplace(float* __restrict__ e, size_t n4)
{
    size_t i = blockIdx.x * (size_t)blockDim.x + threadIdx.x;
    if (i < n4) {
        float4 t = reinterpret_cast<float4*>(e)[i];
        t.x = fmaxf(t.x, 0.f); t.y = fmaxf(t.y, 0.f);
        t.z = fmaxf(t.z, 0.f); t.w = fmaxf(t.w, 0.f);
        reinterpret_cast<float4*>(e)[i] = t;
    }
}

// ----------------------------------------------------------------------------
// Host orchestration. All launches on default stream (graph-capturable).
// Input order (per setup_inputs dict insertion):
//   0 feat0, 1 feat1,
//   2..16: (row,col,val) x {a00,a01,a10,a11a,a11b}
//   17..31: per relation r in {00,01,10,11a,11b}: W1_r, W2_r, W3_r
// ----------------------------------------------------------------------------
extern "C" void kernel_launch(void* const* d_in, const int* in_sizes, int n_in,
                              void* d_out, int out_size)
{
    const float* feat0 = (const float*)d_in[0];
    const float* feat1 = (const float*)d_in[1];

    const int*   a_row[5];
    const int*   a_col[5];
    const float* a_val[5];
    int          Ecnt[5];
    for (int i = 0; i < 5; i++) {
        a_row[i] = (const int*)d_in[2 + 3 * i];
        a_col[i] = (const int*)d_in[3 + 3 * i];
        a_val[i] = (const float*)d_in[4 + 3 * i];
        Ecnt[i]  = in_sizes[2 + 3 * i];
    }
    // W[layer][rel]: rel order 00, 01, 10, 11a, 11b
    const float* W[3][5];
    for (int r = 0; r < 5; r++)
        for (int l = 0; l < 3; l++)
            W[l][r] = (const float*)d_in[17 + 3 * r + l];

    float *tmp, *e00, *e01, *e20, *e21;
    {
        void* p;
        cudaGetSymbolAddress(&p, g_tmp); tmp = (float*)p;
        cudaGetSymbolAddress(&p, g_e00); e00 = (float*)p;
        cudaGetSymbolAddress(&p, g_e01); e01 = (float*)p;
        cudaGetSymbolAddress(&p, g_e20); e20 = (float*)p;
        cudaGetSymbolAddress(&p, g_e21); e21 = (float*)p;
    }
    float* out = (float*)d_out;

    auto gemm = [&](const float* A, const float* Wm, int M, int K) {
        dim3 grid(KH / 128, (M + 127) / 128);
        sgemm128<<<grid, 256>>>(A, Wm, tmp, M, KH, K);
    };
    auto spmm = [&](int rel, float* dst, int ldo) {
        int E = Ecnt[rel];
        spmm_edges<<<(E + 7) / 8, 256>>>(a_row[rel], a_col[rel], a_val[rel],
                                         tmp, dst, E, ldo);
    };
    auto zero = [&](float* p, size_t nelem) {
        size_t n4 = nelem / 4;
        zero_kernel<<<(unsigned)((n4 + 255) / 256), 256>>>(p, n4);
    };

    // ---------------- Layer 1 ----------------
    zero(e00, (size_t)KN0 * KH);
    gemm(feat0, W[0][0], KN0, KF); spmm(0, e00, KH);   // a00
    gemm(feat1, W[0][1], KN1, KF); spmm(1, e00, KH);   // a01
    relu_copy_dual<<<(KN0 * 128 + 255) / 256, 256>>>(e00, out, KN0);

    zero(e01, (size_t)KN1 * KH);
    gemm(feat0, W[0][2], KN0, KF); spmm(2, e01, KH);   // a10
    gemm(feat1, W[0][3], KN1, KF); spmm(3, e01, KH);   // a11a
    gemm(feat1, W[0][4], KN1, KF); spmm(4, e01, KH);   // a11b
    relu_copy_dual<<<(KN1 * 128 + 255) / 256, 256>>>(e01, out + (size_t)KN0 * LDO, KN1);

    // ---------------- Layer 2 (K = H = 512) ----------------
    zero(e20, (size_t)KN0 * KH);
    gemm(e00, W[1][0], KN0, KH); spmm(0, e20, KH);
    gemm(e01, W[1][1], KN1, KH); spmm(1, e20, KH);
    relu_inplace<<<((size_t)KN0 * KH / 4 + 255) / 256, 256>>>(e20, (size_t)KN0 * KH / 4);

    zero(e21, (size_t)KN1 * KH);
    gemm(e00, W[1][2], KN0, KH); spmm(2, e21, KH);
    gemm(e01, W[1][3], KN1, KH); spmm(3, e21, KH);
    gemm(e01, W[1][4], KN1, KH); spmm(4, e21, KH);
    relu_inplace<<<((size_t)KN1 * KH / 4 + 255) / 256, 256>>>(e21, (size_t)KN1 * KH / 4);

    // ---------------- Layer 3 (accumulate straight into d_out cols 1024:1536) ----
    zero_cols<<<((KN0 + KN1) * 128 + 255) / 256, 256>>>(out, KN0 + KN1);
    float* out3_t0 = out + 1024;
    float* out3_t1 = out + (size_t)KN0 * LDO + 1024;
    gemm(e20, W[2][0], KN0, KH); spmm(0, out3_t0, LDO);
    gemm(e21, W[2][1], KN1, KH); spmm(1, out3_t0, LDO);
    gemm(e20, W[2][2], KN0, KH); spmm(2, out3_t1, LDO);
    gemm(e21, W[2][3], KN1, KH); spmm(3, out3_t1, LDO);
    gemm(e21, W[2][4], KN1, KH); spmm(4, out3_t1, LDO);
}

// round 5
// speedup vs baseline: 1.7771x; 1.7771x over previous
#include <cuda_runtime.h>
#include <cuda_bf16.h>
#include <cstdint>
#include <cstddef>

// ============================================================================
// DecagonModel — R5: bf16-split mma.sync GEMMs (compute_100-safe) + COO SpMM
// (R4 with the B-fragment register-order fix: bhf[j] = {klo, khi} per n-group)
// Shapes: N0=30000, N1=6000, F=1024, H=512, out [36000, 1536] f32.
// ============================================================================

#define KN0 30000
#define KN1 6000
#define KF  1024
#define KH  512
#define LDO 1536

// ---------------- device-global scratch (allocation-free rule) --------------
__device__ float g_tmp[KN0 * KH];
__device__ float g_e00[KN0 * KH];
__device__ float g_e01[KN1 * KH];
__device__ float g_e20[KN0 * KH];
__device__ float g_e21[KN1 * KH];

__device__ __nv_bfloat16 g_f0h[KN0 * KF], g_f0l[KN0 * KF];
__device__ __nv_bfloat16 g_f1h[KN1 * KF], g_f1l[KN1 * KF];
__device__ __nv_bfloat16 g_e00h[KN0 * KH], g_e00l[KN0 * KH];
__device__ __nv_bfloat16 g_e01h[KN1 * KH], g_e01l[KN1 * KH];
__device__ __nv_bfloat16 g_e20h[KN0 * KH], g_e20l[KN0 * KH];
__device__ __nv_bfloat16 g_e21h[KN1 * KH], g_e21l[KN1 * KH];

#define WT_TOTAL (5 * KH * KF + 10 * KH * KH)
__device__ __nv_bfloat16 g_wth[WT_TOTAL], g_wtl[WT_TOTAL];

// ---------------- helpers ---------------------------------------------------
__device__ __forceinline__ uint32_t smem_u32(const void* p) {
    uint32_t a;
    asm("{ .reg .u64 t; cvta.to.shared.u64 t, %1; cvt.u32.u64 %0, t; }"
        : "=r"(a) : "l"(p));
    return a;
}
__device__ __forceinline__ void cpa16(uint32_t dst, const void* src, bool v) {
    asm volatile("cp.async.cg.shared.global [%0], [%1], 16, %2;"
                 :: "r"(dst), "l"(src), "r"(v ? 16 : 0) : "memory");
}
__device__ __forceinline__ void ldsm4(uint32_t& r0, uint32_t& r1, uint32_t& r2,
                                      uint32_t& r3, uint32_t addr) {
    asm volatile("ldmatrix.sync.aligned.m8n8.x4.shared.b16 {%0,%1,%2,%3}, [%4];"
                 : "=r"(r0), "=r"(r1), "=r"(r2), "=r"(r3) : "r"(addr));
}
__device__ __forceinline__ void mma16816(float& c0, float& c1, float& c2, float& c3,
                                         uint32_t a0, uint32_t a1, uint32_t a2, uint32_t a3,
                                         uint32_t b0, uint32_t b1) {
    asm volatile(
        "mma.sync.aligned.m16n8k16.row.col.f32.bf16.bf16.f32 "
        "{%0,%1,%2,%3}, {%4,%5,%6,%7}, {%8,%9}, {%0,%1,%2,%3};"
        : "+f"(c0), "+f"(c1), "+f"(c2), "+f"(c3)
        : "r"(a0), "r"(a1), "r"(a2), "r"(a3), "r"(b0), "r"(b1));
}

// smem tile: 128 rows x 32 bf16 (64B rows), XOR swizzle: conflict-free for
// 16B-granule cp.async stores and ldmatrix reads.
__device__ __forceinline__ uint32_t swz(int r, int cbyte) {
    return (uint32_t)(r * 64 + (cbyte ^ (((r >> 1) & 3) << 4)));
}

// ----------------------------------------------------------------------------
// GEMM: C[M,512] = (Ah+Al)[M,K] @ (Bh+Bl)^T, B stored [512,K] bf16 row-major.
// CTA 128x128, BK=32, 3-stage cp.async, 256 threads, warp tile 64x32.
// ----------------------------------------------------------------------------
#define STG_BYTES 32768u          // Ah 8K | Al 8K | Bh 8K | Bl 8K
#define GEMM_SMEM (3 * STG_BYTES)

__global__ __launch_bounds__(256) void gemm_mma(
    const __nv_bfloat16* __restrict__ Ah, const __nv_bfloat16* __restrict__ Al,
    const __nv_bfloat16* __restrict__ Bh, const __nv_bfloat16* __restrict__ Bl,
    float* __restrict__ C, int M, int K)
{
    extern __shared__ char dyn_smem[];
    const uint32_t sbase = smem_u32(dyn_smem);

    const int tid  = threadIdx.x;
    const int wid  = tid >> 5;
    const int lane = tid & 31;
    const int bm   = blockIdx.y * 128;
    const int bn   = blockIdx.x * 128;
    const int wm   = (wid & 1) * 64;
    const int wn   = (wid >> 1) * 32;

    const int NC = K >> 5;

    auto load_stage = [&](int c) {
        const uint32_t st = sbase + (uint32_t)(c % 3) * STG_BYTES;
        const int k0 = c << 5;
#pragma unroll
        for (int it = 0; it < 8; it++) {
            int seg  = it * 256 + tid;
            int reg  = seg >> 9;                 // 0 Ah, 1 Al, 2 Bh, 3 Bl
            int r    = (seg & 511) >> 2;
            int cs   = seg & 3;
            uint32_t dst = st + (uint32_t)reg * 8192u + swz(r, cs * 16);
            const __nv_bfloat16* src;
            bool v = true;
            if (reg < 2) {
                int gr = bm + r;
                v = gr < M; if (!v) gr = 0;
                src = (reg == 0 ? Ah : Al) + (size_t)gr * K + k0 + cs * 8;
            } else {
                src = (reg == 2 ? Bh : Bl) + (size_t)(bn + r) * K + k0 + cs * 8;
            }
            cpa16(dst, src, v);
        }
        asm volatile("cp.async.commit_group;" ::: "memory");
    };

    float acc[4][4][4];
#pragma unroll
    for (int i = 0; i < 4; i++)
#pragma unroll
        for (int j = 0; j < 4; j++)
#pragma unroll
            for (int q = 0; q < 4; q++) acc[i][j][q] = 0.f;

    load_stage(0);
    load_stage(1);

    const int mi  = lane >> 3;
    const int r8  = lane & 7;
    const int aro = (mi & 1) * 8 + r8;     // A: row within 16, kseg by mi>>1
    const int akb = (mi >> 1) * 16;
    const int bro = (mi & 1) * 8 + r8;     // B: n-row within 16, kseg by mi>>1
    const int bkb = (mi >> 1) * 16;

    for (int c = 0; c < NC; c++) {
        asm volatile("cp.async.wait_group 1;" ::: "memory");
        __syncthreads();
        if (c + 2 < NC) load_stage(c + 2);

        const uint32_t st  = sbase + (uint32_t)(c % 3) * STG_BYTES;
        const uint32_t sAh = st, sAl = st + 8192, sBh = st + 16384, sBl = st + 24576;

#pragma unroll
        for (int s = 0; s < 2; s++) {
            const int kb = s * 32;          // byte offset of 16-elem K fragment pair
            uint32_t ah[4][4], al[4][4], bhf[4][2], blf[4][2];
            // A hi: 4 m-tiles of 16 rows. ldmatrix x4 -> a0..a3 exactly.
            #pragma unroll
            for (int i = 0; i < 4; i++)
                ldsm4(ah[i][0], ah[i][1], ah[i][2], ah[i][3],
                      sAh + swz(wm + i * 16 + aro, kb + akb));
            // B hi: j2 covers 16 n; matrices r0=(nlo,klo) r1=(nhi,klo) r2=(nlo,khi) r3=(nhi,khi)
            // mma B frag per 8-n group = {klo, khi}: bhf[2*j2]={r0,r2}, bhf[2*j2+1]={r1,r3}
            #pragma unroll
            for (int j2 = 0; j2 < 2; j2++) {
                uint32_t r0, r1, r2, r3;
                ldsm4(r0, r1, r2, r3, sBh + swz(wn + j2 * 16 + bro, kb + bkb));
                bhf[j2 * 2][0]     = r0; bhf[j2 * 2][1]     = r2;
                bhf[j2 * 2 + 1][0] = r1; bhf[j2 * 2 + 1][1] = r3;
            }
            #pragma unroll
            for (int i = 0; i < 4; i++)
                #pragma unroll
                for (int j = 0; j < 4; j++)
                    mma16816(acc[i][j][0], acc[i][j][1], acc[i][j][2], acc[i][j][3],
                             ah[i][0], ah[i][1], ah[i][2], ah[i][3],
                             bhf[j][0], bhf[j][1]);
            // B lo
            #pragma unroll
            for (int j2 = 0; j2 < 2; j2++) {
                uint32_t r0, r1, r2, r3;
                ldsm4(r0, r1, r2, r3, sBl + swz(wn + j2 * 16 + bro, kb + bkb));
                blf[j2 * 2][0]     = r0; blf[j2 * 2][1]     = r2;
                blf[j2 * 2 + 1][0] = r1; blf[j2 * 2 + 1][1] = r3;
            }
            #pragma unroll
            for (int i = 0; i < 4; i++)
                #pragma unroll
                for (int j = 0; j < 4; j++)
                    mma16816(acc[i][j][0], acc[i][j][1], acc[i][j][2], acc[i][j][3],
                             ah[i][0], ah[i][1], ah[i][2], ah[i][3],
                             blf[j][0], blf[j][1]);
            // A lo x B hi
            #pragma unroll
            for (int i = 0; i < 4; i++)
                ldsm4(al[i][0], al[i][1], al[i][2], al[i][3],
                      sAl + swz(wm + i * 16 + aro, kb + akb));
            #pragma unroll
            for (int i = 0; i < 4; i++)
                #pragma unroll
                for (int j = 0; j < 4; j++)
                    mma16816(acc[i][j][0], acc[i][j][1], acc[i][j][2], acc[i][j][3],
                             al[i][0], al[i][1], al[i][2], al[i][3],
                             bhf[j][0], bhf[j][1]);
        }
        __syncthreads();
    }

    // epilogue: lane holds (m = l/4 [+8], n = 2*(l%4)) per 16x8 tile
    const int lm = lane >> 2, ln = (lane & 3) * 2;
#pragma unroll
    for (int i = 0; i < 4; i++) {
#pragma unroll
        for (int j = 0; j < 4; j++) {
            int m0 = bm + wm + i * 16 + lm;
            int n0 = bn + wn + j * 8 + ln;
            if (m0 < M)
                *(float2*)(C + (size_t)m0 * KH + n0) =
                    make_float2(acc[i][j][0], acc[i][j][1]);
            if (m0 + 8 < M)
                *(float2*)(C + (size_t)(m0 + 8) * KH + n0) =
                    make_float2(acc[i][j][2], acc[i][j][3]);
        }
    }
}

// ----------------------------------------------------------------------------
// SpMM (COO, warp/edge) with red.global.add.v4.f32
// ----------------------------------------------------------------------------
__global__ __launch_bounds__(256) void spmm_edges(
    const int* __restrict__ row, const int* __restrict__ col,
    const float* __restrict__ val, const float* __restrict__ x,
    float* __restrict__ out, int E, int ldo)
{
    int warp = (blockIdx.x * blockDim.x + threadIdx.x) >> 5;
    int lane = threadIdx.x & 31;
    if (warp >= E) return;
    const int   r = row[warp];
    const int   c = col[warp];
    const float v = val[warp];
    const float4* xr   = reinterpret_cast<const float4*>(x + (size_t)c * KH);
    float*        orow = out + (size_t)r * ldo;
#pragma unroll
    for (int i = 0; i < 4; i++) {
        float4 t = xr[lane + i * 32];
        float* p = orow + (size_t)(lane + i * 32) * 4;
        asm volatile("red.global.add.v4.f32 [%0], {%1, %2, %3, %4};"
                     :: "l"(p), "f"(t.x * v), "f"(t.y * v), "f"(t.z * v), "f"(t.w * v)
                     : "memory");
    }
}

// ----------------------------------------------------------------------------
// Converters / epilogues
// ----------------------------------------------------------------------------
__device__ __forceinline__ void split2(float a, float b, __nv_bfloat162& h, __nv_bfloat162& l)
{
    __nv_bfloat16 ha = __float2bfloat16(a), hb = __float2bfloat16(b);
    h = __nv_bfloat162(ha, hb);
    l = __nv_bfloat162(__float2bfloat16(a - __bfloat162float(ha)),
                       __float2bfloat16(b - __bfloat162float(hb)));
}

__global__ void split_k(const float* __restrict__ x,
                        __nv_bfloat16* __restrict__ h, __nv_bfloat16* __restrict__ l, size_t n4)
{
    size_t i = blockIdx.x * (size_t)blockDim.x + threadIdx.x;
    if (i >= n4) return;
    float4 t = reinterpret_cast<const float4*>(x)[i];
    __nv_bfloat162 h0, l0, h1, l1;
    split2(t.x, t.y, h0, l0);
    split2(t.z, t.w, h1, l1);
    reinterpret_cast<__nv_bfloat162*>(h)[i * 2]     = h0;
    reinterpret_cast<__nv_bfloat162*>(h)[i * 2 + 1] = h1;
    reinterpret_cast<__nv_bfloat162*>(l)[i * 2]     = l0;
    reinterpret_cast<__nv_bfloat162*>(l)[i * 2 + 1] = l1;
}

// W [K,512] f32 -> Wt hi/lo [512,K] bf16
__global__ void wt_split(const float* __restrict__ W,
                         __nv_bfloat16* __restrict__ th, __nv_bfloat16* __restrict__ tl, int K)
{
    __shared__ float t[32][33];
    int kb = blockIdx.x * 32, nb = blockIdx.y * 32;
    int x = threadIdx.x, y = threadIdx.y;   // block (32,8)
#pragma unroll
    for (int i = 0; i < 32; i += 8)
        t[y + i][x] = W[(size_t)(kb + y + i) * KH + nb + x];
    __syncthreads();
#pragma unroll
    for (int i = 0; i < 32; i += 8) {
        int n = nb + y + i, k = kb + x;
        float v = t[x][y + i];
        __nv_bfloat16 hb = __float2bfloat16(v);
        th[(size_t)n * K + k] = hb;
        tl[(size_t)n * K + k] = __float2bfloat16(v - __bfloat162float(hb));
    }
}

__global__ void zero_kernel(float* __restrict__ p, size_t n4)
{
    size_t i = blockIdx.x * (size_t)blockDim.x + threadIdx.x;
    if (i < n4) reinterpret_cast<float4*>(p)[i] = make_float4(0.f, 0.f, 0.f, 0.f);
}

__global__ void zero_cols(float* __restrict__ out, int nrows)
{
    int idx = blockIdx.x * blockDim.x + threadIdx.x;
    if (idx >= nrows * 128) return;
    int r = idx >> 7, c = idx & 127;
    reinterpret_cast<float4*>(out + (size_t)r * LDO + 1024)[c] =
        make_float4(0.f, 0.f, 0.f, 0.f);
}

__global__ void relu_dual_split(float* __restrict__ e, float* __restrict__ outbase,
                                __nv_bfloat16* __restrict__ eh, __nv_bfloat16* __restrict__ el,
                                int n)
{
    int idx = blockIdx.x * blockDim.x + threadIdx.x;
    if (idx >= n * 128) return;
    float4 t = reinterpret_cast<float4*>(e)[idx];
    t.x = fmaxf(t.x, 0.f); t.y = fmaxf(t.y, 0.f);
    t.z = fmaxf(t.z, 0.f); t.w = fmaxf(t.w, 0.f);
    reinterpret_cast<float4*>(e)[idx] = t;
    int r = idx >> 7, c = idx & 127;
    float4* o = reinterpret_cast<float4*>(outbase + (size_t)r * LDO);
    o[c]       = t;
    o[c + 128] = t;
    __nv_bfloat162 h0, l0, h1, l1;
    split2(t.x, t.y, h0, l0);
    split2(t.z, t.w, h1, l1);
    reinterpret_cast<__nv_bfloat162*>(eh)[idx * 2]     = h0;
    reinterpret_cast<__nv_bfloat162*>(eh)[idx * 2 + 1] = h1;
    reinterpret_cast<__nv_bfloat162*>(el)[idx * 2]     = l0;
    reinterpret_cast<__nv_bfloat162*>(el)[idx * 2 + 1] = l1;
}

__global__ void relu_split(float* __restrict__ e,
                           __nv_bfloat16* __restrict__ eh, __nv_bfloat16* __restrict__ el,
                           size_t n4)
{
    size_t i = blockIdx.x * (size_t)blockDim.x + threadIdx.x;
    if (i >= n4) return;
    float4 t = reinterpret_cast<float4*>(e)[i];
    t.x = fmaxf(t.x, 0.f); t.y = fmaxf(t.y, 0.f);
    t.z = fmaxf(t.z, 0.f); t.w = fmaxf(t.w, 0.f);
    reinterpret_cast<float4*>(e)[i] = t;
    __nv_bfloat162 h0, l0, h1, l1;
    split2(t.x, t.y, h0, l0);
    split2(t.z, t.w, h1, l1);
    reinterpret_cast<__nv_bfloat162*>(eh)[i * 2]     = h0;
    reinterpret_cast<__nv_bfloat162*>(eh)[i * 2 + 1] = h1;
    reinterpret_cast<__nv_bfloat162*>(el)[i * 2]     = l0;
    reinterpret_cast<__nv_bfloat162*>(el)[i * 2 + 1] = l1;
}

// ----------------------------------------------------------------------------
// Host orchestration
// ----------------------------------------------------------------------------
static size_t wt_off(int l, int r)
{
    if (l == 0) return (size_t)r * KH * KF;
    return (size_t)5 * KH * KF + (size_t)((l - 1) * 5 + r) * KH * KH;
}

extern "C" void kernel_launch(void* const* d_in, const int* in_sizes, int n_in,
                              void* d_out, int out_size)
{
    const float* feat0 = (const float*)d_in[0];
    const float* feat1 = (const float*)d_in[1];

    const int*   a_row[5]; const int* a_col[5]; const float* a_val[5]; int Ecnt[5];
    for (int i = 0; i < 5; i++) {
        a_row[i] = (const int*)d_in[2 + 3 * i];
        a_col[i] = (const int*)d_in[3 + 3 * i];
        a_val[i] = (const float*)d_in[4 + 3 * i];
        Ecnt[i]  = in_sizes[2 + 3 * i];
    }
    const float* W[3][5];
    for (int r = 0; r < 5; r++)
        for (int l = 0; l < 3; l++)
            W[l][r] = (const float*)d_in[17 + 3 * r + l];

    float *tmp, *e00, *e01, *e20, *e21;
    __nv_bfloat16 *f0h, *f0l, *f1h, *f1l;
    __nv_bfloat16 *e00h, *e00l, *e01h, *e01l, *e20h, *e20l, *e21h, *e21l;
    __nv_bfloat16 *wth, *wtl;
    {
        void* p;
        cudaGetSymbolAddress(&p, g_tmp);  tmp  = (float*)p;
        cudaGetSymbolAddress(&p, g_e00);  e00  = (float*)p;
        cudaGetSymbolAddress(&p, g_e01);  e01  = (float*)p;
        cudaGetSymbolAddress(&p, g_e20);  e20  = (float*)p;
        cudaGetSymbolAddress(&p, g_e21);  e21  = (float*)p;
        cudaGetSymbolAddress(&p, g_f0h);  f0h  = (__nv_bfloat16*)p;
        cudaGetSymbolAddress(&p, g_f0l);  f0l  = (__nv_bfloat16*)p;
        cudaGetSymbolAddress(&p, g_f1h);  f1h  = (__nv_bfloat16*)p;
        cudaGetSymbolAddress(&p, g_f1l);  f1l  = (__nv_bfloat16*)p;
        cudaGetSymbolAddress(&p, g_e00h); e00h = (__nv_bfloat16*)p;
        cudaGetSymbolAddress(&p, g_e00l); e00l = (__nv_bfloat16*)p;
        cudaGetSymbolAddress(&p, g_e01h); e01h = (__nv_bfloat16*)p;
        cudaGetSymbolAddress(&p, g_e01l); e01l = (__nv_bfloat16*)p;
        cudaGetSymbolAddress(&p, g_e20h); e20h = (__nv_bfloat16*)p;
        cudaGetSymbolAddress(&p, g_e20l); e20l = (__nv_bfloat16*)p;
        cudaGetSymbolAddress(&p, g_e21h); e21h = (__nv_bfloat16*)p;
        cudaGetSymbolAddress(&p, g_e21l); e21l = (__nv_bfloat16*)p;
        cudaGetSymbolAddress(&p, g_wth);  wth  = (__nv_bfloat16*)p;
        cudaGetSymbolAddress(&p, g_wtl);  wtl  = (__nv_bfloat16*)p;
    }
    float* out = (float*)d_out;

    cudaFuncSetAttribute(gemm_mma, cudaFuncAttributeMaxDynamicSharedMemorySize, GEMM_SMEM);

    // ---- preprocessing: transpose+split weights, split features ----
    for (int r = 0; r < 5; r++)
        wt_split<<<dim3(KF / 32, KH / 32), dim3(32, 8)>>>(W[0][r], wth + wt_off(0, r),
                                                          wtl + wt_off(0, r), KF);
    for (int l = 1; l < 3; l++)
        for (int r = 0; r < 5; r++)
            wt_split<<<dim3(KH / 32, KH / 32), dim3(32, 8)>>>(W[l][r], wth + wt_off(l, r),
                                                              wtl + wt_off(l, r), KH);
    {
        size_t n4 = (size_t)KN0 * KF / 4;
        split_k<<<(unsigned)((n4 + 255) / 256), 256>>>(feat0, f0h, f0l, n4);
        n4 = (size_t)KN1 * KF / 4;
        split_k<<<(unsigned)((n4 + 255) / 256), 256>>>(feat1, f1h, f1l, n4);
    }

    auto gemm = [&](const __nv_bfloat16* Ah, const __nv_bfloat16* Al,
                    int l, int r, int M, int K) {
        dim3 grid(4, (M + 127) / 128);
        gemm_mma<<<grid, 256, GEMM_SMEM>>>(Ah, Al, wth + wt_off(l, r), wtl + wt_off(l, r),
                                           tmp, M, K);
    };
    auto spmm = [&](int rel, float* dst, int ldo) {
        int E = Ecnt[rel];
        spmm_edges<<<(E + 7) / 8, 256>>>(a_row[rel], a_col[rel], a_val[rel], tmp, dst, E, ldo);
    };
    auto zero = [&](float* p, size_t nelem) {
        size_t n4 = nelem / 4;
        zero_kernel<<<(unsigned)((n4 + 255) / 256), 256>>>(p, n4);
    };

    // ---------------- Layer 1 (K = F = 1024) ----------------
    zero(e00, (size_t)KN0 * KH);
    gemm(f0h, f0l, 0, 0, KN0, KF); spmm(0, e00, KH);
    gemm(f1h, f1l, 0, 1, KN1, KF); spmm(1, e00, KH);
    relu_dual_split<<<(KN0 * 128 + 255) / 256, 256>>>(e00, out, e00h, e00l, KN0);

    zero(e01, (size_t)KN1 * KH);
    gemm(f0h, f0l, 0, 2, KN0, KF); spmm(2, e01, KH);
    gemm(f1h, f1l, 0, 3, KN1, KF); spmm(3, e01, KH);
    gemm(f1h, f1l, 0, 4, KN1, KF); spmm(4, e01, KH);
    relu_dual_split<<<(KN1 * 128 + 255) / 256, 256>>>(e01, out + (size_t)KN0 * LDO,
                                                      e01h, e01l, KN1);

    // ---------------- Layer 2 (K = H = 512) ----------------
    zero(e20, (size_t)KN0 * KH);
    gemm(e00h, e00l, 1, 0, KN0, KH); spmm(0, e20, KH);
    gemm(e01h, e01l, 1, 1, KN1, KH); spmm(1, e20, KH);
    relu_split<<<((size_t)KN0 * KH / 4 + 255) / 256, 256>>>(e20, e20h, e20l,
                                                            (size_t)KN0 * KH / 4);

    zero(e21, (size_t)KN1 * KH);
    gemm(e00h, e00l, 1, 2, KN0, KH); spmm(2, e21, KH);
    gemm(e01h, e01l, 1, 3, KN1, KH); spmm(3, e21, KH);
    gemm(e01h, e01l, 1, 4, KN1, KH); spmm(4, e21, KH);
    relu_split<<<((size_t)KN1 * KH / 4 + 255) / 256, 256>>>(e21, e21h, e21l,
                                                            (size_t)KN1 * KH / 4);

    // ---------------- Layer 3 (into d_out cols 1024:1536) ----------------
    zero_cols<<<((KN0 + KN1) * 128 + 255) / 256, 256>>>(out, KN0 + KN1);
    float* out3_t0 = out + 1024;
    float* out3_t1 = out + (size_t)KN0 * LDO + 1024;
    gemm(e20h, e20l, 2, 0, KN0, KH); spmm(0, out3_t0, LDO);
    gemm(e21h, e21l, 2, 1, KN1, KH); spmm(1, out3_t0, LDO);
    gemm(e20h, e20l, 2, 2, KN0, KH); spmm(2, out3_t1, LDO);
    gemm(e21h, e21l, 2, 3, KN1, KH); spmm(3, out3_t1, LDO);
    gemm(e21h, e21l, 2, 4, KN1, KH); spmm(4, out3_t1, LDO);
}